// round 7
// baseline (speedup 1.0000x reference)
#include <cuda_runtime.h>
#include <math.h>

// dims
#define E    256
#define H    128
#define NQ   8
#define QED  64
#define HYP  64
#define NA   14
#define NAG  8
#define BS   4096
#define BSG  512
#define WSZ  32768

// output layout: sorted_q [BS,NA,NQ] | h [BS,H] | rq [BSG,NQ]
#define OFF_SQ 0
#define OFF_H  (BS*NA*NQ)
#define OFF_RQ (OFF_H + BS*H)

// scratch
__device__ __align__(16) float g_msm[2*H];
__device__ __align__(16) float g_W[H*2*H];        // [128][256]
__device__ __align__(16) float g_wrz[2*H*2*H];    // [256][256]
__device__ __align__(16) float g_wn[H*2*H];       // [128][256]
__device__ __align__(16) float g_qphi[BSG*NQ*H];

typedef unsigned long long u64t;
__device__ __forceinline__ u64t pk2(float a) {
    u64t r; asm("mov.b64 %0, {%1,%1};" : "=l"(r) : "f"(a)); return r;
}
__device__ __forceinline__ u64t pk2b(float a, float b) {
    u64t r; asm("mov.b64 %0, {%1,%2};" : "=l"(r) : "f"(a), "f"(b)); return r;
}
__device__ __forceinline__ void fma2(u64t& d, u64t a, u64t b) {
    asm("fma.rn.f32x2 %0, %1, %2, %3;" : "=l"(d) : "l"(a), "l"(b), "l"(d));
}
__device__ __forceinline__ float2 upk(u64t v) {
    float2 f; asm("mov.b64 {%0,%1}, %2;" : "=f"(f.x), "=f"(f.y) : "l"(v)); return f;
}
__device__ __forceinline__ float sigm(float x) {
    return __fdividef(1.f, 1.f + __expf(-x));
}

// cp.async helpers
__device__ __forceinline__ void cpa16(unsigned s, const void* g) {
    asm volatile("cp.async.cg.shared.global [%0], [%1], 16;" :: "r"(s), "l"(g));
}
__device__ __forceinline__ void cpcommit() { asm volatile("cp.async.commit_group;"); }
__device__ __forceinline__ void cpwait1()  { asm volatile("cp.async.wait_group 1;"); }
__device__ __forceinline__ void cpwait0()  { asm volatile("cp.async.wait_group 0;"); }

// ---------------------------------------------------------------------------
// merged weight-prep + qphi kernel. 256 threads/block. (unchanged from R6)
__global__ __launch_bounds__(256)
void k_wprep(const float* __restrict__ hyp_w1,
             const float* __restrict__ hyp_b1,
             const float* __restrict__ hyp_w2,
             const float* __restrict__ hyp_b2,
             const float* __restrict__ merger_w,
             const float* __restrict__ gwi,
             const float* __restrict__ gwh,
             const float* __restrict__ rq,
             const float* __restrict__ phi_w,
             const float* __restrict__ phi_b,
             float* __restrict__ out) {
    int bid = blockIdx.x, t = threadIdx.x;
    if (bid < 128) {
        __shared__ float sh[HYP];
        __shared__ float4 sred[256];
        if (t < HYP) {
            float s = hyp_b1[t];
            #pragma unroll
            for (int q = 0; q < NQ; q++) s += hyp_w1[q*HYP + t];
            sh[t] = fmaxf(s, 0.f);
        }
        __syncthreads();
        int m4loc = t & 63, fc = t >> 6;
        int m4 = bid*64 + m4loc;
        const float4* src = (const float4*)hyp_w2;
        float4 acc = make_float4(0.f, 0.f, 0.f, 0.f);
        #pragma unroll
        for (int f = 0; f < 16; f++) {
            float s = sh[fc*16 + f];
            float4 v = src[(fc*16 + f)*8192 + m4];
            acc.x = fmaf(s, v.x, acc.x);
            acc.y = fmaf(s, v.y, acc.y);
            acc.z = fmaf(s, v.z, acc.z);
            acc.w = fmaf(s, v.w, acc.w);
        }
        sred[t] = acc;
        __syncthreads();
        if (fc == 0) {
            float4 a = sred[t], b = sred[t+64], c = sred[t+128], d = sred[t+192];
            float4 bi = ((const float4*)hyp_b2)[m4];
            float4 r;
            r.x = a.x + b.x + c.x + d.x + bi.x;
            r.y = a.y + b.y + c.y + d.y + bi.y;
            r.z = a.z + b.z + c.z + d.z + bi.z;
            r.w = a.w + b.w + c.w + d.w + bi.w;
            ((float4*)g_W)[m4] = r;
        }
    } else if (bid < 384) {
        int idx = (bid - 128)*256 + t;
        int k = idx >> 8, j = idx & 255;
        g_wrz[idx] = (k < 128) ? gwi[j*128 + k] : gwh[j*128 + (k - 128)];
    } else if (bid < 512) {
        int idx = (bid - 384)*256 + t;
        int k = idx >> 8, j = idx & 255;
        g_wn[idx] = (j < 128) ? gwi[(256 + j)*128 + k] : gwh[(128 + j)*128 + k];
    } else if (bid == 512) {
        if (t < H) {
            float a = merger_w[t], b = merger_w[H + t];
            float m = fmaxf(a, b);
            float e0 = expf(a - m), e1 = expf(b - m);
            float inv = 1.f / (e0 + e1);
            g_msm[t]     = e0 * inv;
            g_msm[H + t] = e1 * inv;
        }
    } else {
        __shared__ float c[QED];
        int r = bid - 513;
        float rqv = rq[r];
        if (t < QED) c[t] = cospif((float)t * rqv);
        if (t == 0) out[OFF_RQ + r] = rqv;
        __syncthreads();
        if (t < H) {
            float acc = phi_b[t];
            #pragma unroll 8
            for (int f = 0; f < QED; f++) acc = fmaf(c[f], phi_w[f*H + t], acc);
            g_qphi[r*H + t] = fmaxf(acc, 0.f);
        }
    }
}

// ---------------------------------------------------------------------------
// fused main: fc1 -> emb -> merge -> GRU -> fc2 -> sort.
// 256 threads, 16 rows/block, 256 blocks, 2 CTAs/SM.
// thread: rowA = tid&15 (1 row); cg = tid>>4 (0..15); c0 = cg*8.
#define ROWS 16
#define SC_STR 257
#define SX_STR 129
#define SC_F (ROWS*SC_STR)
#define SX_F (ROWS*SX_STR)
#define SB_F (3*4096)
#define SMEM_BYTES ((SC_F + SX_F + SB_F)*4)

__device__ __forceinline__ void stage16k(unsigned sbu, int bufi,
                                         const float* src, int tid) {
    unsigned d = sbu + (unsigned)(bufi*16384 + tid*16);
    const char* s = (const char*)src + tid*16;
    #pragma unroll
    for (int i = 0; i < 4; i++) cpa16(d + i*4096, s + i*4096);
}

__global__ __launch_bounds__(256, 2)
void k_main(const float* __restrict__ in, const float* __restrict__ hprev,
            const float* __restrict__ fc1_w, const float* __restrict__ fc1_b,
            const float* __restrict__ gbi,  const float* __restrict__ gbh,
            const float* __restrict__ fc2_w, const float* __restrict__ fc2_b,
            float* __restrict__ out) {
    extern __shared__ float smem[];
    float* sC = smem;
    float* sX = smem + SC_F;
    float* sB = smem + SC_F + SX_F;
    unsigned sbu = (unsigned)__cvta_generic_to_shared(sB);

    const int tid  = threadIdx.x;
    const int rowA = tid & 15;
    const int c0   = (tid >> 4) * 8;        // 0..120
    const int row0 = blockIdx.x * ROWS;

    // stage input A [16][256] -> sC
    {
        const float4* src = (const float4*)(in + row0*E);
        #pragma unroll
        for (int i = tid; i < 1024; i += 256) {
            float4 v = src[i];
            int f = i * 4;
            int r = f >> 8, cc = f & 255;
            float* p = sC + r*SC_STR + cc;
            p[0] = v.x; p[1] = v.y; p[2] = v.z; p[3] = v.w;
        }
    }
    stage16k(sbu, 0, fc1_w, tid); cpcommit();

    // ======== FC1 : tiles g=0..7, KT=32, width 128 ========
    u64t X[4];
    {
        float4 b0 = *(const float4*)(fc1_b + c0);
        float4 b1 = *(const float4*)(fc1_b + c0 + 4);
        X[0] = pk2b(b0.x, b0.y); X[1] = pk2b(b0.z, b0.w);
        X[2] = pk2b(b1.x, b1.y); X[3] = pk2b(b1.z, b1.w);
    }
    #pragma unroll 1
    for (int t = 0; t < 8; t++) {
        int g = t;
        const float* nsrc = (t < 7) ? (fc1_w + (t+1)*4096) : g_W;
        stage16k(sbu, (g+1)%3, nsrc, tid); cpcommit();
        cpwait1();
        __syncthreads();
        const float* bw  = sB + (g%3)*4096;
        const float* a0p = sC + rowA*SC_STR + t*32;
        #pragma unroll 8
        for (int kk = 0; kk < 32; kk++) {
            const float* wr = bw + kk*128 + c0;
            ulonglong2 w01 = *(const ulonglong2*)wr;
            ulonglong2 w23 = *(const ulonglong2*)(wr + 4);
            u64t a0 = pk2(a0p[kk]);
            fma2(X[0], a0, w01.x); fma2(X[1], a0, w01.y);
            fma2(X[2], a0, w23.x); fma2(X[3], a0, w23.y);
        }
    }
    {
        float* xo = sX + rowA*SX_STR + c0;
        #pragma unroll
        for (int cc = 0; cc < 4; cc++) {
            float2 v = upk(X[cc]);
            xo[2*cc]   = fmaxf(v.x, 0.f);
            xo[2*cc+1] = fmaxf(v.y, 0.f);
        }
    }

    // ======== EMB : tiles g=8..15, KT=16, width 256 ========
    u64t P[4] = {0,0,0,0}, Q[4] = {0,0,0,0};
    #pragma unroll 1
    for (int t = 0; t < 8; t++) {
        int g = 8 + t;
        const float* nsrc = (t < 7) ? (g_W + (t+1)*4096) : g_wrz;
        stage16k(sbu, (g+1)%3, nsrc, tid); cpcommit();
        cpwait1();
        __syncthreads();
        const float* bw  = sB + (g%3)*4096;
        const float* a0p = sX + rowA*SX_STR + t*16;
        #pragma unroll 4
        for (int kk = 0; kk < 16; kk++) {
            const float* wr0 = bw + kk*256 + c0;
            ulonglong2 p01 = *(const ulonglong2*)wr0;
            ulonglong2 p23 = *(const ulonglong2*)(wr0 + 4);
            ulonglong2 q01 = *(const ulonglong2*)(wr0 + 128);
            ulonglong2 q23 = *(const ulonglong2*)(wr0 + 132);
            u64t a0 = pk2(a0p[kk]);
            fma2(P[0], a0, p01.x); fma2(P[1], a0, p01.y);
            fma2(P[2], a0, p23.x); fma2(P[3], a0, p23.y);
            fma2(Q[0], a0, q01.x); fma2(Q[1], a0, q01.y);
            fma2(Q[2], a0, q23.x); fma2(Q[3], a0, q23.y);
        }
    }

    // ---- merge + relu -> x2 into sC[0,128); stage hprev -> sC[128,256)
    {
        float4 m0a = *(const float4*)(g_msm + c0);
        float4 m0b = *(const float4*)(g_msm + c0 + 4);
        float4 m1a = *(const float4*)(g_msm + H + c0);
        float4 m1b = *(const float4*)(g_msm + H + c0 + 4);
        float m0v[8] = {m0a.x,m0a.y,m0a.z,m0a.w,m0b.x,m0b.y,m0b.z,m0b.w};
        float m1v[8] = {m1a.x,m1a.y,m1a.z,m1a.w,m1b.x,m1b.y,m1b.z,m1b.w};
        float* co = sC + rowA*SC_STR + c0;
        #pragma unroll
        for (int cc = 0; cc < 4; cc++) {
            float2 a = upk(P[cc]); float2 b = upk(Q[cc]);
            co[2*cc]   = fmaxf(fmaf(m0v[2*cc],   a.x, m1v[2*cc]  *b.x), 0.f);
            co[2*cc+1] = fmaxf(fmaf(m0v[2*cc+1], a.y, m1v[2*cc+1]*b.y), 0.f);
        }
        const float4* hsrc = (const float4*)(hprev + row0*H);
        #pragma unroll
        for (int i = tid; i < 512; i += 256) {
            float4 v = hsrc[i];
            int f = i * 4;
            int r = f >> 7, cc = f & 127;
            float* p = sC + r*SC_STR + 128 + cc;
            p[0] = v.x; p[1] = v.y; p[2] = v.z; p[3] = v.w;
        }
    }

    // ======== GRU r,z : tiles g=16..31, KT=16, width 256 ========
    float rs[8], zs[8];
    {
        u64t R[4], Z[4];
        {
            float4 bi0 = *(const float4*)(gbi + c0);
            float4 bi1 = *(const float4*)(gbi + c0 + 4);
            float4 bh0 = *(const float4*)(gbh + c0);
            float4 bh1 = *(const float4*)(gbh + c0 + 4);
            R[0] = pk2b(bi0.x+bh0.x, bi0.y+bh0.y);
            R[1] = pk2b(bi0.z+bh0.z, bi0.w+bh0.w);
            R[2] = pk2b(bi1.x+bh1.x, bi1.y+bh1.y);
            R[3] = pk2b(bi1.z+bh1.z, bi1.w+bh1.w);
            float4 ci0 = *(const float4*)(gbi + H + c0);
            float4 ci1 = *(const float4*)(gbi + H + c0 + 4);
            float4 ch0 = *(const float4*)(gbh + H + c0);
            float4 ch1 = *(const float4*)(gbh + H + c0 + 4);
            Z[0] = pk2b(ci0.x+ch0.x, ci0.y+ch0.y);
            Z[1] = pk2b(ci0.z+ch0.z, ci0.w+ch0.w);
            Z[2] = pk2b(ci1.x+ch1.x, ci1.y+ch1.y);
            Z[3] = pk2b(ci1.z+ch1.z, ci1.w+ch1.w);
        }
        #pragma unroll 1
        for (int t = 0; t < 16; t++) {
            int g = 16 + t;
            const float* nsrc = (t < 15) ? (g_wrz + (t+1)*4096) : g_wn;
            stage16k(sbu, (g+1)%3, nsrc, tid); cpcommit();
            cpwait1();
            __syncthreads();
            const float* bw  = sB + (g%3)*4096;
            const float* a0p = sC + rowA*SC_STR + t*16;
            #pragma unroll 4
            for (int kk = 0; kk < 16; kk++) {
                const float* wr0 = bw + kk*256 + c0;
                ulonglong2 p01 = *(const ulonglong2*)wr0;
                ulonglong2 p23 = *(const ulonglong2*)(wr0 + 4);
                ulonglong2 q01 = *(const ulonglong2*)(wr0 + 128);
                ulonglong2 q23 = *(const ulonglong2*)(wr0 + 132);
                u64t a0 = pk2(a0p[kk]);
                fma2(R[0], a0, p01.x); fma2(R[1], a0, p01.y);
                fma2(R[2], a0, p23.x); fma2(R[3], a0, p23.y);
                fma2(Z[0], a0, q01.x); fma2(Z[1], a0, q01.y);
                fma2(Z[2], a0, q23.x); fma2(Z[3], a0, q23.y);
            }
        }
        #pragma unroll
        for (int cc = 0; cc < 4; cc++) {
            float2 rv = upk(R[cc]); float2 zv = upk(Z[cc]);
            rs[2*cc] = sigm(rv.x); rs[2*cc+1] = sigm(rv.y);
            zs[2*cc] = sigm(zv.x); zs[2*cc+1] = sigm(zv.y);
        }
    }

    // ======== GRU n : tiles g=32..39, KT=16, width 256 ========
    {
        u64t N[4], G[4];
        {
            float4 ni0 = *(const float4*)(gbi + 2*H + c0);
            float4 ni1 = *(const float4*)(gbi + 2*H + c0 + 4);
            float4 nh0 = *(const float4*)(gbh + 2*H + c0);
            float4 nh1 = *(const float4*)(gbh + 2*H + c0 + 4);
            N[0] = pk2b(ni0.x, ni0.y); N[1] = pk2b(ni0.z, ni0.w);
            N[2] = pk2b(ni1.x, ni1.y); N[3] = pk2b(ni1.z, ni1.w);
            G[0] = pk2b(nh0.x, nh0.y); G[1] = pk2b(nh0.z, nh0.w);
            G[2] = pk2b(nh1.x, nh1.y); G[3] = pk2b(nh1.z, nh1.w);
        }
        #pragma unroll 1
        for (int t = 0; t < 8; t++) {
            int g = 32 + t;
            if (t < 7) { stage16k(sbu, (g+1)%3, g_wn + (t+1)*4096, tid); cpcommit(); cpwait1(); }
            else cpwait0();
            __syncthreads();
            const float* bw  = sB + (g%3)*4096;
            const float* a0p = sC + rowA*SC_STR + t*16;
            #pragma unroll 4
            for (int kk = 0; kk < 16; kk++) {
                const float* wr0 = bw + kk*256 + c0;
                ulonglong2 p01 = *(const ulonglong2*)wr0;
                ulonglong2 p23 = *(const ulonglong2*)(wr0 + 4);
                ulonglong2 q01 = *(const ulonglong2*)(wr0 + 128);
                ulonglong2 q23 = *(const ulonglong2*)(wr0 + 132);
                u64t x0 = pk2(a0p[kk]);
                u64t h0 = pk2(a0p[kk + 128]);
                fma2(N[0], x0, p01.x); fma2(N[1], x0, p01.y);
                fma2(N[2], x0, p23.x); fma2(N[3], x0, p23.y);
                fma2(G[0], h0, q01.x); fma2(G[1], h0, q01.y);
                fma2(G[2], h0, q23.x); fma2(G[3], h0, q23.y);
            }
        }

        // finalize h
        float hv[8];
        const float* hp = sC + rowA*SC_STR + 128 + c0;
        #pragma unroll
        for (int cc = 0; cc < 4; cc++) {
            float2 nv = upk(N[cc]); float2 gv = upk(G[cc]);
            float n0 = tanhf(fmaf(rs[2*cc],   gv.x, nv.x));
            float n1 = tanhf(fmaf(rs[2*cc+1], gv.y, nv.y));
            hv[2*cc]   = (1.f - zs[2*cc])  * n0 + zs[2*cc]  * hp[2*cc];
            hv[2*cc+1] = (1.f - zs[2*cc+1])* n1 + zs[2*cc+1]* hp[2*cc+1];
        }
        int rg = row0 + rowA;
        *(float4*)&out[OFF_H + rg*H + c0]     = make_float4(hv[0], hv[1], hv[2], hv[3]);
        *(float4*)&out[OFF_H + rg*H + c0 + 4] = make_float4(hv[4], hv[5], hv[6], hv[7]);

        __syncthreads();           // all reads of sC (x2/hp) done

        float* ho = sC + rowA*SC_STR + c0;
        #pragma unroll
        for (int cc = 0; cc < 8; cc++) ho[cc] = hv[cc];
    }

    // ======== epilogue: fc2 + transpose + sort ========
    // sB[0..2064): qphi tile [16][129] ; sB+4224: ssq [16][112]
    // sX[0..2048): fc2_w padded [128][16]
    {
        float* sQ = sB;
        float* sW = sX;
        float* ssq = sB + 4224;
        #pragma unroll
        for (int i = tid; i < 2048; i += 256) {
            int qq = i >> 7, j = i & 127;
            sQ[qq*129 + j] = g_qphi[(row0 + qq)*H + j];
        }
        for (int i = tid; i < H*NA; i += 256) {
            int j = i / NA, na = i - j*NA;
            sW[j*16 + na] = fc2_w[i];
        }
        __syncthreads();

        if (tid < 128) {
            const int row = tid & 15;
            const int qi  = tid >> 4;        // 0..7
            const float* hrow = sC + row*SC_STR;
            const float* qrow = sQ + ((row >> 3)*8 + qi)*129;
            u64t acc[7];
            #pragma unroll
            for (int p = 0; p < 7; p++) acc[p] = pk2b(fc2_b[2*p], fc2_b[2*p+1]);
            #pragma unroll 4
            for (int j = 0; j < H; j++) {
                float hq = hrow[j] * qrow[j];
                u64t h2 = pk2(hq);
                const ulonglong2* wp = (const ulonglong2*)(sW + j*16);
                ulonglong2 w0 = wp[0], w1 = wp[1];
                u64t w2 = *(const u64t*)(sW + j*16 + 8);
                u64t w3 = *(const u64t*)(sW + j*16 + 10);
                u64t w4 = *(const u64t*)(sW + j*16 + 12);
                fma2(acc[0], h2, w0.x); fma2(acc[1], h2, w0.y);
                fma2(acc[2], h2, w1.x); fma2(acc[3], h2, w1.y);
                fma2(acc[4], h2, w2);   fma2(acc[5], h2, w3);
                fma2(acc[6], h2, w4);
            }
            #pragma unroll
            for (int p = 0; p < 7; p++) {
                float2 v = upk(acc[p]);
                ssq[row*112 + (2*p)*8   + qi] = v.x;
                ssq[row*112 + (2*p+1)*8 + qi] = v.y;
            }
        }
        __syncthreads();

        // sort: 224 (row,na) pairs
        for (int p = tid; p < ROWS*NA; p += 256) {
            int r = p / NA, na = p - r*NA;
            const float* s = ssq + r*112 + na*8;
            float v[NQ];
            #pragma unroll
            for (int k = 0; k < NQ; k++) v[k] = s[k];
            #pragma unroll
            for (int i = 1; i < NQ; i++) {
                float key = v[i];
                int q = i - 1;
                while (q >= 0 && v[q] > key) { v[q+1] = v[q]; q--; }
                v[q+1] = key;
            }
            float* o = out + OFF_SQ + (row0 + r)*112 + na*8;
            *(float4*)o       = make_float4(v[0], v[1], v[2], v[3]);
            *(float4*)(o + 4) = make_float4(v[4], v[5], v[6], v[7]);
        }
    }
}

// ---------------------------------------------------------------------------
extern "C" void kernel_launch(void* const* d_in, const int* in_sizes, int n_in,
                              void* d_out, int out_size) {
    const float* in        = (const float*)d_in[0];
    const float* hidden    = (const float*)d_in[1];
    const float* rqs       = (const float*)d_in[2];
    const float* fc1_w     = (const float*)d_in[3];
    const float* fc1_b     = (const float*)d_in[4];
    const float* hyp_w1    = (const float*)d_in[5];
    const float* hyp_b1    = (const float*)d_in[6];
    const float* hyp_w2    = (const float*)d_in[7];
    const float* hyp_b2    = (const float*)d_in[8];
    const float* merger_w  = (const float*)d_in[9];
    const float* gru_wi    = (const float*)d_in[10];
    const float* gru_wh    = (const float*)d_in[11];
    const float* gru_bi    = (const float*)d_in[12];
    const float* gru_bh    = (const float*)d_in[13];
    const float* phi_w     = (const float*)d_in[14];
    const float* phi_b     = (const float*)d_in[15];
    const float* fc2_w     = (const float*)d_in[16];
    const float* fc2_b     = (const float*)d_in[17];
    float* out = (float*)d_out;

    static int smem_set = 0;
    if (!smem_set) {
        cudaFuncSetAttribute(k_main, cudaFuncAttributeMaxDynamicSharedMemorySize,
                             SMEM_BYTES);
        smem_set = 1;
    }

    k_wprep<<<513 + BSG*NQ, 256>>>(hyp_w1, hyp_b1, hyp_w2, hyp_b2, merger_w,
                                   gru_wi, gru_wh, rqs, phi_w, phi_b, out);
    k_main<<<BS/ROWS, 256, SMEM_BYTES>>>(in, hidden, fc1_w, fc1_b, gru_bi, gru_bh,
                                         fc2_w, fc2_b, out);
}